// round 1
// baseline (speedup 1.0000x reference)
#include <cuda_runtime.h>
#include <math.h>

#define NN 100000
#define EE 1600000
#define FD 128
#define OD 32
#define NEG 0.2f
#define FULL 0xffffffffu

// BN scale factor 1/sqrt(1+1e-5)
#define BNS 0.9999950000374997f

// ---------------- scratch (static device globals; no allocation) ----------------
__device__ float g_h1[(size_t)NN * FD];     // layer1 pre-attention features
__device__ float g_as1[NN * 4];             // alpha_src layer1 per head
__device__ float g_ad1[NN * 4];             // alpha_dst layer1 per head
__device__ float g_h2[(size_t)NN * OD];     // layer2 pre-attention features
__device__ float g_as2[NN];
__device__ float g_ad2[NN];
__device__ int   g_cnt[NN];                 // in-degree (excl self loop)
__device__ int   g_off[NN];                 // CSR offsets
__device__ int   g_cur[NN];                 // scatter cursors
__device__ int   g_esrc[EE];                // src ids grouped by dst
__device__ int   g_bsum[128];
__device__ int   g_bofs[128];

__device__ __forceinline__ float lrelu(float v) { return v > 0.f ? v : NEG * v; }

__device__ __forceinline__ float sel4(float a, float b, float c, float d, int h) {
    float r = a;
    r = (h == 1) ? b : r;
    r = (h == 2) ? c : r;
    r = (h == 3) ? d : r;
    return r;
}

// ---------------- kernels ----------------

__global__ void k_zero() {
    int i = blockIdx.x * blockDim.x + threadIdx.x;
    if (i < NN) g_cnt[i] = 0;
}

// h1 = x @ W1 ; block computes 64-row x 128-col tile, full K=128 in smem
__global__ void k_gemm1(const float* __restrict__ x, const float* __restrict__ W1) {
    extern __shared__ float sm[];
    float* ws = sm;            // 128*128
    float* xs = sm + 128 * 128; // 64*128
    int tid = threadIdx.x;     // 256
    int row0 = blockIdx.x * 64;

    for (int i = tid; i < 4096; i += 256)
        ((float4*)ws)[i] = ((const float4*)W1)[i];
    for (int i = tid; i < 2048; i += 256) {
        int r = i >> 5, c = i & 31;
        int gr = row0 + r;
        float4 v = make_float4(0.f, 0.f, 0.f, 0.f);
        if (gr < NN) v = ((const float4*)x)[(size_t)gr * 32 + c];
        ((float4*)(xs + r * 128))[c] = v;
    }
    __syncthreads();

    int tx = tid & 31, ty = tid >> 5;
    float4 acc[8];
#pragma unroll
    for (int r = 0; r < 8; r++) acc[r] = make_float4(0.f, 0.f, 0.f, 0.f);
    const float* xrow = xs + (ty * 8) * 128;

#pragma unroll 4
    for (int k = 0; k < 128; k++) {
        float4 b = ((float4*)(ws + k * 128))[tx];
#pragma unroll
        for (int r = 0; r < 8; r++) {
            float a = xrow[r * 128 + k];
            acc[r].x = fmaf(a, b.x, acc[r].x);
            acc[r].y = fmaf(a, b.y, acc[r].y);
            acc[r].z = fmaf(a, b.z, acc[r].z);
            acc[r].w = fmaf(a, b.w, acc[r].w);
        }
    }
#pragma unroll
    for (int r = 0; r < 8; r++) {
        int gr = row0 + ty * 8 + r;
        if (gr < NN) ((float4*)(g_h1 + (size_t)gr * 128))[tx] = acc[r];
    }
}

// per-node attention coefficients for layer1 (warp per node)
__global__ void k_alpha1(const float* __restrict__ a1s, const float* __restrict__ a1d) {
    int w = (blockIdx.x * blockDim.x + threadIdx.x) >> 5;
    int lane = threadIdx.x & 31;
    if (w >= NN) return;
    float4 h = ((const float4*)(g_h1 + (size_t)w * 128))[lane];
    float4 as = ((const float4*)a1s)[lane];
    float4 ad = ((const float4*)a1d)[lane];
    float ps = h.x * as.x + h.y * as.y + h.z * as.z + h.w * as.w;
    float pd = h.x * ad.x + h.y * ad.y + h.z * ad.z + h.w * ad.w;
#pragma unroll
    for (int d = 4; d; d >>= 1) {
        ps += __shfl_down_sync(FULL, ps, d);
        pd += __shfl_down_sync(FULL, pd, d);
    }
    if ((lane & 7) == 0) {
        int head = lane >> 3;
        g_as1[w * 4 + head] = ps;
        g_ad1[w * 4 + head] = pd;
    }
}

__global__ void k_hist(const int* __restrict__ ei) {
    int e = blockIdx.x * blockDim.x + threadIdx.x;
    if (e < EE) atomicAdd(&g_cnt[ei[EE + e]], 1);
}

__global__ void k_scan1() {
    int b = blockIdx.x, tid = threadIdx.x;
    int i = b * 1024 + tid;
    int v = (i < NN) ? g_cnt[i] : 0;
    int orig = v;
    int lane = tid & 31, wid = tid >> 5;
#pragma unroll
    for (int d = 1; d < 32; d <<= 1) {
        int t = __shfl_up_sync(FULL, v, d);
        if (lane >= d) v += t;
    }
    __shared__ int wsum[32];
    if (lane == 31) wsum[wid] = v;
    __syncthreads();
    if (wid == 0) {
        int w2 = wsum[lane];
#pragma unroll
        for (int d = 1; d < 32; d <<= 1) {
            int t = __shfl_up_sync(FULL, w2, d);
            if (lane >= d) w2 += t;
        }
        wsum[lane] = w2;
    }
    __syncthreads();
    int base = (wid > 0) ? wsum[wid - 1] : 0;
    int incl = v + base;
    if (i < NN) g_off[i] = incl - orig;
    if (tid == 1023) g_bsum[b] = incl;
}

__global__ void k_scan2(int nb) {
    __shared__ int s[128];
    int tid = threadIdx.x;
    s[tid] = (tid < nb) ? g_bsum[tid] : 0;
    __syncthreads();
    if (tid == 0) {
        int run = 0;
        for (int j = 0; j < nb; j++) { int t = s[j]; s[j] = run; run += t; }
    }
    __syncthreads();
    if (tid < nb) g_bofs[tid] = s[tid];
}

__global__ void k_scan3() {
    int i = blockIdx.x * blockDim.x + threadIdx.x;
    if (i < NN) {
        int o = g_off[i] + g_bofs[i >> 10];
        g_off[i] = o;
        g_cur[i] = o;
    }
}

__global__ void k_scatter(const int* __restrict__ ei) {
    int e = blockIdx.x * blockDim.x + threadIdx.x;
    if (e < EE) {
        int s = ei[e], d = ei[EE + e];
        int p = atomicAdd(&g_cur[d], 1);
        g_esrc[p] = s;
    }
}

// deterministic per-segment sort by src value (warp per node; rank sort)
__global__ void k_sort() {
    int w = (blockIdx.x * blockDim.x + threadIdx.x) >> 5;
    int lane = threadIdx.x & 31;
    if (w >= NN) return;
    int s0 = g_off[w], deg = g_cnt[w];
    if (deg <= 1) return;
    int vi[8], rk[8];
    int t = 0;
    for (int i = lane; i < deg && t < 8; i += 32, t++) {
        int v = g_esrc[s0 + i];
        int r = 0;
        for (int j = 0; j < deg; j++) {
            int u = g_esrc[s0 + j];
            r += (u < v) || (u == v && j < i);
        }
        vi[t] = v;
        rk[t] = r;
    }
    __syncwarp();
    t = 0;
    for (int i = lane; i < deg && t < 8; i += 32, t++)
        g_esrc[s0 + rk[t]] = vi[t];
}

// layer1 segment softmax + aggregate + b1 + BN + ELU + fused GEMM2 + layer2 attn coeffs
__global__ void k_agg1(const float* __restrict__ b1, const float* __restrict__ gam,
                       const float* __restrict__ bet, const float* __restrict__ W2,
                       const float* __restrict__ a2s, const float* __restrict__ a2d) {
    __shared__ float W2s[128 * 32];
    int tid = threadIdx.x;
    for (int i = tid; i < 1024; i += 256)
        ((float4*)W2s)[i] = ((const float4*)W2)[i];
    __syncthreads();

    int w = (blockIdx.x * 256 + tid) >> 5;
    int lane = tid & 31;
    if (w >= NN) return;
    int s0 = g_off[w], deg = g_cnt[w];

    float4 adn = ((const float4*)g_ad1)[w];
    float4 asn = ((const float4*)g_as1)[w];
    float es0 = lrelu(asn.x + adn.x), es1 = lrelu(asn.y + adn.y);
    float es2 = lrelu(asn.z + adn.z), es3 = lrelu(asn.w + adn.w);
    float m0 = es0, m1 = es1, m2 = es2, m3 = es3;

    for (int i = lane; i < deg; i += 32) {
        int s = g_esrc[s0 + i];
        float4 a = ((const float4*)g_as1)[s];
        m0 = fmaxf(m0, lrelu(a.x + adn.x));
        m1 = fmaxf(m1, lrelu(a.y + adn.y));
        m2 = fmaxf(m2, lrelu(a.z + adn.z));
        m3 = fmaxf(m3, lrelu(a.w + adn.w));
    }
#pragma unroll
    for (int d = 16; d; d >>= 1) {
        m0 = fmaxf(m0, __shfl_xor_sync(FULL, m0, d));
        m1 = fmaxf(m1, __shfl_xor_sync(FULL, m1, d));
        m2 = fmaxf(m2, __shfl_xor_sync(FULL, m2, d));
        m3 = fmaxf(m3, __shfl_xor_sync(FULL, m3, d));
    }

    float p0 = 0.f, p1 = 0.f, p2 = 0.f, p3 = 0.f;
    for (int i = lane; i < deg; i += 32) {
        int s = g_esrc[s0 + i];
        float4 a = ((const float4*)g_as1)[s];
        p0 += expf(lrelu(a.x + adn.x) - m0);
        p1 += expf(lrelu(a.y + adn.y) - m1);
        p2 += expf(lrelu(a.z + adn.z) - m2);
        p3 += expf(lrelu(a.w + adn.w) - m3);
    }
#pragma unroll
    for (int d = 16; d; d >>= 1) {
        p0 += __shfl_xor_sync(FULL, p0, d);
        p1 += __shfl_xor_sync(FULL, p1, d);
        p2 += __shfl_xor_sync(FULL, p2, d);
        p3 += __shfl_xor_sync(FULL, p3, d);
    }
    p0 += expf(es0 - m0); p1 += expf(es1 - m1);
    p2 += expf(es2 - m2); p3 += expf(es3 - m3);
    float i0 = 1.f / (p0 + 1e-16f), i1 = 1.f / (p1 + 1e-16f);
    float i2 = 1.f / (p2 + 1e-16f), i3 = 1.f / (p3 + 1e-16f);

    // lane owns channels c = lane*4 .. lane*4+3, all within head h = lane>>3
    int h = lane >> 3;
    float mh  = sel4(m0, m1, m2, m3, h);
    float ih  = sel4(i0, i1, i2, i3, h);
    float adh = sel4(adn.x, adn.y, adn.z, adn.w, h);
    float esh = sel4(es0, es1, es2, es3, h);

    float aself = expf(esh - mh) * ih;
    float4 hv = ((const float4*)(g_h1 + (size_t)w * 128))[lane];
    float4 acc;
    acc.x = aself * hv.x; acc.y = aself * hv.y;
    acc.z = aself * hv.z; acc.w = aself * hv.w;

    for (int j = 0; j < deg; j++) {
        int s = g_esrc[s0 + j];
        float4 a = ((const float4*)g_as1)[s];
        float ash = sel4(a.x, a.y, a.z, a.w, h);
        float alpha = expf(lrelu(ash + adh) - mh) * ih;
        float4 v = ((const float4*)(g_h1 + (size_t)s * 128))[lane];
        acc.x = fmaf(alpha, v.x, acc.x);
        acc.y = fmaf(alpha, v.y, acc.y);
        acc.z = fmaf(alpha, v.z, acc.z);
        acc.w = fmaf(alpha, v.w, acc.w);
    }

    // epilogue: +b1, BN(eval), ELU
    float4 bb = ((const float4*)b1)[lane];
    float4 g4 = ((const float4*)gam)[lane];
    float4 be = ((const float4*)bet)[lane];
    acc.x = (acc.x + bb.x) * (g4.x * BNS) + be.x;
    acc.y = (acc.y + bb.y) * (g4.y * BNS) + be.y;
    acc.z = (acc.z + bb.z) * (g4.z * BNS) + be.z;
    acc.w = (acc.w + bb.w) * (g4.w * BNS) + be.w;
    acc.x = acc.x > 0.f ? acc.x : expm1f(acc.x);
    acc.y = acc.y > 0.f ? acc.y : expm1f(acc.y);
    acc.z = acc.z > 0.f ? acc.z : expm1f(acc.z);
    acc.w = acc.w > 0.f ? acc.w : expm1f(acc.w);

    // fused GEMM2: h2[o=lane] = sum_c act[c] * W2[c][o]
    float h2v = 0.f;
#pragma unroll
    for (int cb = 0; cb < 32; cb++) {
        float bx = __shfl_sync(FULL, acc.x, cb);
        float by = __shfl_sync(FULL, acc.y, cb);
        float bz = __shfl_sync(FULL, acc.z, cb);
        float bw = __shfl_sync(FULL, acc.w, cb);
        const float* wc = W2s + (cb * 4) * 32 + lane;
        h2v = fmaf(bx, wc[0],  h2v);
        h2v = fmaf(by, wc[32], h2v);
        h2v = fmaf(bz, wc[64], h2v);
        h2v = fmaf(bw, wc[96], h2v);
    }
    g_h2[(size_t)w * 32 + lane] = h2v;

    float ps = h2v * a2s[lane];
    float pd = h2v * a2d[lane];
#pragma unroll
    for (int d = 16; d; d >>= 1) {
        ps += __shfl_xor_sync(FULL, ps, d);
        pd += __shfl_xor_sync(FULL, pd, d);
    }
    if (lane == 0) { g_as2[w] = ps; g_ad2[w] = pd; }
}

// layer2 segment softmax + aggregate + b2 -> out
__global__ void k_agg2(const float* __restrict__ b2, float* __restrict__ out) {
    int w = (blockIdx.x * blockDim.x + threadIdx.x) >> 5;
    int lane = threadIdx.x & 31;
    if (w >= NN) return;
    int s0 = g_off[w], deg = g_cnt[w];
    float adn = g_ad2[w];
    float es = lrelu(g_as2[w] + adn);
    float m = es;
    for (int i = lane; i < deg; i += 32)
        m = fmaxf(m, lrelu(g_as2[g_esrc[s0 + i]] + adn));
#pragma unroll
    for (int d = 16; d; d >>= 1)
        m = fmaxf(m, __shfl_xor_sync(FULL, m, d));
    float p = 0.f;
    for (int i = lane; i < deg; i += 32)
        p += expf(lrelu(g_as2[g_esrc[s0 + i]] + adn) - m);
#pragma unroll
    for (int d = 16; d; d >>= 1)
        p += __shfl_xor_sync(FULL, p, d);
    p += expf(es - m);
    float inv = 1.f / (p + 1e-16f);
    float acc = expf(es - m) * inv * g_h2[(size_t)w * 32 + lane];
    for (int j = 0; j < deg; j++) {
        int s = g_esrc[s0 + j];
        float alpha = expf(lrelu(g_as2[s] + adn) - m) * inv;
        acc = fmaf(alpha, g_h2[(size_t)s * 32 + lane], acc);
    }
    out[(size_t)w * 32 + lane] = acc + b2[lane];
}

// ---------------- launch ----------------
extern "C" void kernel_launch(void* const* d_in, const int* in_sizes, int n_in,
                              void* d_out, int out_size) {
    const float* x   = (const float*)d_in[0];
    const int*   ei  = (const int*)d_in[1];
    const float* W1  = (const float*)d_in[2];
    const float* a1s = (const float*)d_in[3];
    const float* a1d = (const float*)d_in[4];
    const float* b1  = (const float*)d_in[5];
    const float* gam = (const float*)d_in[6];
    const float* bet = (const float*)d_in[7];
    const float* W2  = (const float*)d_in[8];
    const float* a2s = (const float*)d_in[9];
    const float* a2d = (const float*)d_in[10];
    const float* b2  = (const float*)d_in[11];
    float* out = (float*)d_out;

    cudaFuncSetAttribute(k_gemm1, cudaFuncAttributeMaxDynamicSharedMemorySize, 98304);

    int nb = (NN + 1023) / 1024;
    k_zero<<<(NN + 255) / 256, 256>>>();
    k_gemm1<<<(NN + 63) / 64, 256, 98304>>>(x, W1);
    k_alpha1<<<(NN * 32 + 255) / 256, 256>>>(a1s, a1d);
    k_hist<<<(EE + 255) / 256, 256>>>(ei);
    k_scan1<<<nb, 1024>>>();
    k_scan2<<<1, 128>>>(nb);
    k_scan3<<<(NN + 255) / 256, 256>>>();
    k_scatter<<<(EE + 255) / 256, 256>>>(ei);
    k_sort<<<(NN * 32 + 255) / 256, 256>>>();
    k_agg1<<<(NN * 32 + 255) / 256, 256>>>(b1, gam, bet, W2, a2s, a2d);
    k_agg2<<<(NN * 32 + 255) / 256, 256>>>(b2, out);
}